// round 11
// baseline (speedup 1.0000x reference)
#include <cuda_runtime.h>
#include <cuda_bf16.h>
#include <math.h>
#include <stdint.h>

#define BATCH 4096
#define D     512
#define NROW  8192          // 2B
#define TS    128           // CTA tile (square)
#define KCB   128           // k chunk in BYTES (= 128 s8 elements)
#define NCH   (D / KCB)     // 4 chunks
#define NT    (NROW / TS)   // 64
#define NTRI  (NT * (NT + 1) / 2)       // 2080 CTAs
#define AB_BYTES (TS * 128)             // 16384 per operand per stage
#define STAGE_BYTES (2 * AB_BYTES)      // 32768
#define NSTAGE 3
#define SMEM_TOTAL (NSTAGE * STAGE_BYTES)  // 98304

// ---- scratch (__device__ globals: allocation-free rule) ----
__device__ int8_t g_xq[NROW * D];   // per-row-quantized [e1;e2], 4 MB
__device__ float g_u[NROW];         // invt_i / s_i
__device__ float g_v[NROW];         // 1 / s_i
__device__ float g_pos[NROW];
__device__ float g_denom[NROW];

__device__ __forceinline__ uint32_t smem_u32(const void* p) {
    uint32_t a;
    asm("{ .reg .u64 t; cvta.to.shared.u64 t, %1; cvt.u32.u64 %0, t; }"
        : "=r"(a) : "l"(p));
    return a;
}
__device__ __forceinline__ void cp_async16(uint32_t dst, const void* src) {
    asm volatile("cp.async.cg.shared.global [%0], [%1], 16;"
                 :: "r"(dst), "l"(src) : "memory");
}
#define CP_COMMIT() asm volatile("cp.async.commit_group;" ::: "memory")

#define LDM_X4(r, addr)                                                     \
    asm volatile("ldmatrix.sync.aligned.m8n8.x4.shared.b16 {%0,%1,%2,%3}, [%4];" \
                 : "=r"(r[0]), "=r"(r[1]), "=r"(r[2]), "=r"(r[3]) : "r"(addr))

#define MMAS8(d, a, b)                                                      \
    asm volatile("mma.sync.aligned.m16n8k32.row.col.s32.s8.s8.s32 "         \
                 "{%0,%1,%2,%3}, {%4,%5,%6,%7}, {%8,%9}, {%0,%1,%2,%3};"    \
                 : "+r"(d[0]), "+r"(d[1]), "+r"(d[2]), "+r"(d[3])           \
                 : "r"(a[0]), "r"(a[1]), "r"(a[2]), "r"(a[3]),              \
                   "r"(b[0]), "r"(b[1]))

// ---- prep: warp-per-row, shfl-only reduces, int8 quantize ----
__global__ void __launch_bounds__(256) prep_kernel(const float* __restrict__ emb1,
                                                   const float* __restrict__ emb2,
                                                   const float* __restrict__ att) {
    int warp = (blockIdx.x * 256 + threadIdx.x) >> 5;   // row b
    int lane = threadIdx.x & 31;
    if (warp >= BATCH) return;
    int b = warp;

    const float4* a4 = (const float4*)(emb1 + (size_t)b * D);
    const float4* c4 = (const float4*)(emb2 + (size_t)b * D);
    const float4* t4 = (const float4*)(att  + (size_t)b * 256);

    float4 av[4], cv[4];
    float s1 = 0.0f, s2 = 0.0f, sd = 0.0f, sa = 0.0f;
    float m1 = 0.0f, m2 = 0.0f;
    #pragma unroll
    for (int k = 0; k < 4; k++) {
        int f = lane + k * 32;
        av[k] = a4[f]; cv[k] = c4[f];
        s1 += av[k].x*av[k].x + av[k].y*av[k].y + av[k].z*av[k].z + av[k].w*av[k].w;
        s2 += cv[k].x*cv[k].x + cv[k].y*cv[k].y + cv[k].z*cv[k].z + cv[k].w*cv[k].w;
        sd += av[k].x*cv[k].x + av[k].y*cv[k].y + av[k].z*cv[k].z + av[k].w*cv[k].w;
        m1 = fmaxf(m1, fmaxf(fmaxf(fabsf(av[k].x), fabsf(av[k].y)),
                             fmaxf(fabsf(av[k].z), fabsf(av[k].w))));
        m2 = fmaxf(m2, fmaxf(fmaxf(fabsf(cv[k].x), fabsf(cv[k].y)),
                             fmaxf(fabsf(cv[k].z), fabsf(cv[k].w))));
    }
    #pragma unroll
    for (int k = 0; k < 2; k++) {
        float4 v = t4[lane + k * 32];
        sa += v.x + v.y + v.z + v.w;
    }
    #pragma unroll
    for (int o = 16; o > 0; o >>= 1) {
        s1 += __shfl_xor_sync(0xFFFFFFFFu, s1, o);
        s2 += __shfl_xor_sync(0xFFFFFFFFu, s2, o);
        sd += __shfl_xor_sync(0xFFFFFFFFu, sd, o);
        sa += __shfl_xor_sync(0xFFFFFFFFu, sa, o);
        m1 = fmaxf(m1, __shfl_xor_sync(0xFFFFFFFFu, m1, o));
        m2 = fmaxf(m2, __shfl_xor_sync(0xFFFFFFFFu, m2, o));
    }

    float r1 = 1.0f / fmaxf(sqrtf(s1), 1e-12f);
    float r2 = 1.0f / fmaxf(sqrtf(s2), 1e-12f);
    float invt = 1.0f / (0.07f * (1.0f + 0.5f * (sa * (1.0f / 256.0f))));

    // quant scales on NORMALIZED rows: max|x| = m*r
    float mx1 = fmaxf(m1 * r1, 1e-12f);
    float mx2 = fmaxf(m2 * r2, 1e-12f);
    float sc1 = 127.0f / mx1, sc2 = 127.0f / mx2;      // quant scale
    float q1 = sc1 * r1, q2 = sc2 * r2;                // applied to raw elems

    uint32_t* x1 = (uint32_t*)(g_xq + (size_t)b * D);
    uint32_t* x2 = (uint32_t*)(g_xq + (size_t)(b + BATCH) * D);
    #pragma unroll
    for (int k = 0; k < 4; k++) {
        int f = lane + k * 32;
        int qa0 = __float2int_rn(av[k].x * q1), qa1 = __float2int_rn(av[k].y * q1);
        int qa2 = __float2int_rn(av[k].z * q1), qa3 = __float2int_rn(av[k].w * q1);
        x1[f] = (uint32_t)(qa0 & 0xFF) | ((uint32_t)(qa1 & 0xFF) << 8) |
                ((uint32_t)(qa2 & 0xFF) << 16) | ((uint32_t)qa3 << 24);
        int qc0 = __float2int_rn(cv[k].x * q2), qc1 = __float2int_rn(cv[k].y * q2);
        int qc2 = __float2int_rn(cv[k].z * q2), qc3 = __float2int_rn(cv[k].w * q2);
        x2[f] = (uint32_t)(qc0 & 0xFF) | ((uint32_t)(qc1 & 0xFF) << 8) |
                ((uint32_t)(qc2 & 0xFF) << 16) | ((uint32_t)qc3 << 24);
    }
    if (lane == 0) {
        float f1 = 1.0f / sc1, f2 = 1.0f / sc2;        // = mx/127
        g_u[b] = invt * f1;  g_u[b + BATCH] = invt * f2;
        g_v[b] = f1;         g_v[b + BATCH] = f2;
        float p = sd * r1 * r2 * invt;
        g_pos[b] = p;        g_pos[b + BATCH] = p;
        g_denom[b] = 0.0f;   g_denom[b + BATCH] = 0.0f;
    }
}

// swizzled byte offset within a 128-row x 128-byte operand buffer
__device__ __forceinline__ uint32_t swz(int row, int c16) {
    return (uint32_t)(row * 128 + ((c16 ^ (row & 7)) * 16));
}

__device__ __forceinline__ void load_stage(uint32_t base,
                                           const int8_t* Xa,
                                           const int8_t* Xb,
                                           int chunk, int tid) {
    #pragma unroll
    for (int it = 0; it < 8; it++) {
        int idx = tid + it * 256;          // 0..2047
        int isA = idx < 1024;
        int j = isA ? idx : idx - 1024;
        int row = j >> 3, c16 = j & 7;
        const int8_t* src = (isA ? Xa : Xb) + (size_t)row * D + chunk * KCB + c16 * 16;
        uint32_t dst = base + (isA ? 0u : (uint32_t)AB_BYTES) + swz(row, c16);
        cp_async16(dst, src);
    }
    CP_COMMIT();
}

// ---- s8 HMMA GEMM tile (128x128) + fused exp row/col-sum epilogue ----
__global__ void __launch_bounds__(256, 2) gemm_exp_kernel() {
    // triangular 1D grid -> (ti, tj), ti <= tj
    int idx = blockIdx.x;
    int ti = (int)((129.0f - sqrtf(16641.0f - 8.0f * (float)idx)) * 0.5f);
    while (ti * (129 - ti) / 2 > idx) ti--;
    while ((ti + 1) * (129 - (ti + 1)) / 2 <= idx) ti++;
    int tj = ti + (idx - ti * (129 - ti) / 2);

    extern __shared__ char smem[];
    uint32_t sb = smem_u32(smem);
    int tid = threadIdx.x;
    int wid = tid >> 5, lane = tid & 31;
    int wm = wid >> 2, wn = wid & 3;       // warp tile: rows wm*64, cols wn*32

    const int8_t* Xa = g_xq + (size_t)ti * TS * D;
    const int8_t* Xb = g_xq + (size_t)tj * TS * D;

    int acc[4][4][4];
    #pragma unroll
    for (int mt = 0; mt < 4; mt++)
        #pragma unroll
        for (int nf = 0; nf < 4; nf++)
            #pragma unroll
            for (int q = 0; q < 4; q++) acc[mt][nf][q] = 0;

    int a_row = wm * 64 + (lane & 7) + ((lane >> 3) & 1) * 8;  // + mt*16
    int a_ch  = (lane >> 4);                                    // + k32*2
    int b_row = wn * 32 + (lane & 7) + ((lane >> 4) & 1) * 8;  // + nt2*16
    int b_ch  = ((lane >> 3) & 1);                              // + k32*2

    load_stage(sb + 0 * STAGE_BYTES, Xa, Xb, 0, tid);
    load_stage(sb + 1 * STAGE_BYTES, Xa, Xb, 1, tid);

    #pragma unroll 1
    for (int c = 0; c < NCH; c++) {
        if (c + 1 < NCH)
            asm volatile("cp.async.wait_group 1;" ::: "memory");
        else
            asm volatile("cp.async.wait_group 0;" ::: "memory");
        __syncthreads();

        if (c + 2 < NCH)
            load_stage(sb + ((c + 2) % NSTAGE) * STAGE_BYTES, Xa, Xb, c + 2, tid);

        uint32_t abase = sb + (c % NSTAGE) * STAGE_BYTES;
        uint32_t bbase = abase + AB_BYTES;
        #pragma unroll
        for (int k32 = 0; k32 < KCB / 32; k32++) {
            uint32_t a_r[4][4], b_r[2][4];
            #pragma unroll
            for (int mt = 0; mt < 4; mt++)
                LDM_X4(a_r[mt], abase + swz(a_row + mt * 16, k32 * 2 + a_ch));
            #pragma unroll
            for (int nt2 = 0; nt2 < 2; nt2++)
                LDM_X4(b_r[nt2], bbase + swz(b_row + nt2 * 16, k32 * 2 + b_ch));
            #pragma unroll
            for (int mt = 0; mt < 4; mt++)
                #pragma unroll
                for (int nt2 = 0; nt2 < 2; nt2++) {
                    MMAS8(acc[mt][nt2 * 2 + 0], a_r[mt], (b_r[nt2] + 0));
                    MMAS8(acc[mt][nt2 * 2 + 1], a_r[mt], (b_r[nt2] + 2));
                }
        }
        // no bottom sync: next iteration's top sync guards stage reuse
    }

    // ---- epilogue: exponent = acc * u_i * v_j (rows), acc * u_j * v_i (cols)
    int lr = lane >> 2;          // 0..7
    int lc = lane & 3;           // 0..3
    int gr0 = ti * TS + wm * 64 + lr;            // + mt*16, +8 for half
    int gc0 = tj * TS + wn * 32 + lc * 2;        // + nf*8, +1

    float vj[4][2], uj[4][2];
    #pragma unroll
    for (int nf = 0; nf < 4; nf++) {
        int gj = gc0 + nf * 8;
        vj[nf][0] = g_v[gj];     vj[nf][1] = g_v[gj + 1];
        uj[nf][0] = g_u[gj];     uj[nf][1] = g_u[gj + 1];
    }

    if (ti == tj) {
        #pragma unroll
        for (int mt = 0; mt < 4; mt++) {
            int gi0 = gr0 + mt * 16, gi1 = gi0 + 8;
            float u0 = g_u[gi0], u1 = g_u[gi1];
            float s0 = 0.0f, s1 = 0.0f;
            #pragma unroll
            for (int nf = 0; nf < 4; nf++) {
                int gj = gc0 + nf * 8;
                float e;
                e = __expf((float)acc[mt][nf][0] * u0 * vj[nf][0]); if (gj     == gi0) e = 0.0f; s0 += e;
                e = __expf((float)acc[mt][nf][1] * u0 * vj[nf][1]); if (gj + 1 == gi0) e = 0.0f; s0 += e;
                e = __expf((float)acc[mt][nf][2] * u1 * vj[nf][0]); if (gj     == gi1) e = 0.0f; s1 += e;
                e = __expf((float)acc[mt][nf][3] * u1 * vj[nf][1]); if (gj + 1 == gi1) e = 0.0f; s1 += e;
            }
            s0 += __shfl_xor_sync(0xFFFFFFFFu, s0, 1);
            s0 += __shfl_xor_sync(0xFFFFFFFFu, s0, 2);
            s1 += __shfl_xor_sync(0xFFFFFFFFu, s1, 1);
            s1 += __shfl_xor_sync(0xFFFFFFFFu, s1, 2);
            if (lc == 0) {
                atomicAdd(&g_denom[gi0], s0);
                atomicAdd(&g_denom[gi1], s1);
            }
        }
    } else {
        float colsum[4][2];
        #pragma unroll
        for (int nf = 0; nf < 4; nf++) { colsum[nf][0] = 0.0f; colsum[nf][1] = 0.0f; }

        #pragma unroll
        for (int mt = 0; mt < 4; mt++) {
            int gi0 = gr0 + mt * 16, gi1 = gi0 + 8;
            float u0 = g_u[gi0], u1 = g_u[gi1];
            float w0 = g_v[gi0], w1 = g_v[gi1];
            float s0 = 0.0f, s1 = 0.0f;
            #pragma unroll
            for (int nf = 0; nf < 4; nf++) {
                float v0 = (float)acc[mt][nf][0], v1 = (float)acc[mt][nf][1];
                float v2 = (float)acc[mt][nf][2], v3 = (float)acc[mt][nf][3];
                s0 += __expf(v0 * u0 * vj[nf][0]) + __expf(v1 * u0 * vj[nf][1]);
                s1 += __expf(v2 * u1 * vj[nf][0]) + __expf(v3 * u1 * vj[nf][1]);
                colsum[nf][0] += __expf(v0 * uj[nf][0] * w0) + __expf(v2 * uj[nf][0] * w1);
                colsum[nf][1] += __expf(v1 * uj[nf][1] * w0) + __expf(v3 * uj[nf][1] * w1);
            }
            s0 += __shfl_xor_sync(0xFFFFFFFFu, s0, 1);
            s0 += __shfl_xor_sync(0xFFFFFFFFu, s0, 2);
            s1 += __shfl_xor_sync(0xFFFFFFFFu, s1, 1);
            s1 += __shfl_xor_sync(0xFFFFFFFFu, s1, 2);
            if (lc == 0) {
                atomicAdd(&g_denom[gi0], s0);
                atomicAdd(&g_denom[gi1], s1);
            }
        }
        #pragma unroll
        for (int nf = 0; nf < 4; nf++) {
            #pragma unroll
            for (int i = 0; i < 2; i++) {
                float cs = colsum[nf][i];
                cs += __shfl_xor_sync(0xFFFFFFFFu, cs, 4);
                cs += __shfl_xor_sync(0xFFFFFFFFu, cs, 8);
                cs += __shfl_xor_sync(0xFFFFFFFFu, cs, 16);
                if (lr == 0)
                    atomicAdd(&g_denom[gc0 + nf * 8 + i], cs);
            }
        }
    }
}

__global__ void __launch_bounds__(1024) final_kernel(float* __restrict__ out) {
    __shared__ float sbuf[32];
    int t = threadIdx.x;
    float s = 0.0f;
    #pragma unroll
    for (int k = 0; k < NROW / 1024; k++) {
        int i = t + k * 1024;
        s += __logf(g_denom[i]) - g_pos[i];
    }
    #pragma unroll
    for (int o = 16; o > 0; o >>= 1) s += __shfl_xor_sync(0xFFFFFFFFu, s, o);
    if ((t & 31) == 0) sbuf[t >> 5] = s;
    __syncthreads();
    if (t < 32) {
        float r = sbuf[t];
        #pragma unroll
        for (int o = 16; o > 0; o >>= 1) r += __shfl_xor_sync(0xFFFFFFFFu, r, o);
        if (t == 0) out[0] = r * (1.0f / NROW);
    }
}

extern "C" void kernel_launch(void* const* d_in, const int* in_sizes, int n_in,
                              void* d_out, int out_size) {
    const float* emb1 = (const float*)d_in[0];
    const float* emb2 = (const float*)d_in[1];
    const float* att  = (const float*)d_in[2];

    cudaFuncSetAttribute(gemm_exp_kernel,
                         cudaFuncAttributeMaxDynamicSharedMemorySize, SMEM_TOTAL);

    prep_kernel<<<BATCH / 8, 256>>>(emb1, emb2, att);
    gemm_exp_kernel<<<NTRI, 256, SMEM_TOTAL>>>();
    final_kernel<<<1, 1024>>>((float*)d_out);
}

// round 14
// speedup vs baseline: 2.0939x; 2.0939x over previous
#include <cuda_runtime.h>
#include <cuda_bf16.h>
#include <math.h>
#include <stdint.h>

#define BATCH 4096
#define D     512
#define NROW  8192          // 2B
#define TSM   128           // CTA tile rows
#define TSN   256           // CTA tile cols
#define KC    64            // k chunk (bf16 elems) = 128 bytes/row
#define NCH   (D / KC)      // 8
#define NCTA  1056          // sum_{cj=0..31} (2cj+2)
#define A_BYTES (TSM * 128)            // 16384
#define B_BYTES (TSN * 128)            // 32768
#define STAGE_BYTES (A_BYTES + B_BYTES) // 49152
#define NSTAGE 3
#define SMEM_TOTAL (NSTAGE * STAGE_BYTES)  // 147456

// ---- scratch (__device__ globals: allocation-free rule) ----
__device__ __nv_bfloat16 g_xb[NROW * D];   // normalized [e1;e2] bf16, 8 MB
__device__ float g_inv_t[NROW];
__device__ float g_pos[NROW];
__device__ float g_denom[NROW];

__device__ __forceinline__ uint32_t smem_u32(const void* p) {
    uint32_t a;
    asm("{ .reg .u64 t; cvta.to.shared.u64 t, %1; cvt.u32.u64 %0, t; }"
        : "=r"(a) : "l"(p));
    return a;
}
__device__ __forceinline__ void cp_async16(uint32_t dst, const void* src) {
    asm volatile("cp.async.cg.shared.global [%0], [%1], 16;"
                 :: "r"(dst), "l"(src) : "memory");
}
#define CP_COMMIT() asm volatile("cp.async.commit_group;" ::: "memory")

#define LDM_X4(r, addr)                                                     \
    asm volatile("ldmatrix.sync.aligned.m8n8.x4.shared.b16 {%0,%1,%2,%3}, [%4];" \
                 : "=r"(r[0]), "=r"(r[1]), "=r"(r[2]), "=r"(r[3]) : "r"(addr))

#define MMA16816(d, a, b)                                                   \
    asm volatile("mma.sync.aligned.m16n8k16.row.col.f32.bf16.bf16.f32 "     \
                 "{%0,%1,%2,%3}, {%4,%5,%6,%7}, {%8,%9}, {%0,%1,%2,%3};"    \
                 : "+f"(d[0]), "+f"(d[1]), "+f"(d[2]), "+f"(d[3])           \
                 : "r"(a[0]), "r"(a[1]), "r"(a[2]), "r"(a[3]),              \
                   "r"(b[0]), "r"(b[1]))

// ---- prep: warp-per-row, shfl-only reduces ----
__global__ void __launch_bounds__(256) prep_kernel(const float* __restrict__ emb1,
                                                   const float* __restrict__ emb2,
                                                   const float* __restrict__ att) {
    int warp = (blockIdx.x * 256 + threadIdx.x) >> 5;   // row b
    int lane = threadIdx.x & 31;
    if (warp >= BATCH) return;
    int b = warp;

    const float4* a4 = (const float4*)(emb1 + (size_t)b * D);
    const float4* c4 = (const float4*)(emb2 + (size_t)b * D);
    const float4* t4 = (const float4*)(att  + (size_t)b * 256);

    float4 av[4], cv[4];
    float s1 = 0.0f, s2 = 0.0f, sd = 0.0f, sa = 0.0f;
    #pragma unroll
    for (int k = 0; k < 4; k++) {
        int f = lane + k * 32;
        av[k] = a4[f]; cv[k] = c4[f];
        s1 += av[k].x*av[k].x + av[k].y*av[k].y + av[k].z*av[k].z + av[k].w*av[k].w;
        s2 += cv[k].x*cv[k].x + cv[k].y*cv[k].y + cv[k].z*cv[k].z + cv[k].w*cv[k].w;
        sd += av[k].x*cv[k].x + av[k].y*cv[k].y + av[k].z*cv[k].z + av[k].w*cv[k].w;
    }
    #pragma unroll
    for (int k = 0; k < 2; k++) {
        float4 v = t4[lane + k * 32];
        sa += v.x + v.y + v.z + v.w;
    }
    #pragma unroll
    for (int o = 16; o > 0; o >>= 1) {
        s1 += __shfl_xor_sync(0xFFFFFFFFu, s1, o);
        s2 += __shfl_xor_sync(0xFFFFFFFFu, s2, o);
        sd += __shfl_xor_sync(0xFFFFFFFFu, sd, o);
        sa += __shfl_xor_sync(0xFFFFFFFFu, sa, o);
    }

    float r1 = 1.0f / fmaxf(sqrtf(s1), 1e-12f);
    float r2 = 1.0f / fmaxf(sqrtf(s2), 1e-12f);
    float invt = 1.0f / (0.07f * (1.0f + 0.5f * (sa * (1.0f / 256.0f))));

    uint2* x1 = (uint2*)(g_xb + (size_t)b * D);
    uint2* x2 = (uint2*)(g_xb + (size_t)(b + BATCH) * D);
    #pragma unroll
    for (int k = 0; k < 4; k++) {
        int f = lane + k * 32;
        __nv_bfloat162 p0 = __floats2bfloat162_rn(av[k].x * r1, av[k].y * r1);
        __nv_bfloat162 p1 = __floats2bfloat162_rn(av[k].z * r1, av[k].w * r1);
        uint2 u; u.x = *(uint32_t*)&p0; u.y = *(uint32_t*)&p1;
        x1[f] = u;
        p0 = __floats2bfloat162_rn(cv[k].x * r2, cv[k].y * r2);
        p1 = __floats2bfloat162_rn(cv[k].z * r2, cv[k].w * r2);
        u.x = *(uint32_t*)&p0; u.y = *(uint32_t*)&p1;
        x2[f] = u;
    }
    if (lane == 0) {
        g_inv_t[b] = invt;  g_inv_t[b + BATCH] = invt;
        float p = sd * r1 * r2 * invt;
        g_pos[b] = p;       g_pos[b + BATCH] = p;
        g_denom[b] = 0.0f;  g_denom[b + BATCH] = 0.0f;
    }
}

// swizzled byte offset within an N-row x 128-byte operand buffer
__device__ __forceinline__ uint32_t swz(int row, int c16) {
    return (uint32_t)(row * 128 + ((c16 ^ (row & 7)) * 16));
}

__device__ __forceinline__ void load_stage(uint32_t base,
                                           const __nv_bfloat16* Xa,
                                           const __nv_bfloat16* Xb,
                                           int chunk, int tid) {
    #pragma unroll
    for (int it = 0; it < 12; it++) {
        int idx = tid + it * 256;          // 0..3071
        int isA = idx < 1024;              // A: 128 rows x 8, B: 256 rows x 8
        int j = isA ? idx : idx - 1024;
        int row = j >> 3, c16 = j & 7;
        const __nv_bfloat16* src =
            (isA ? Xa : Xb) + (size_t)row * D + chunk * KC + c16 * 8;
        uint32_t dst = base + (isA ? 0u : (uint32_t)A_BYTES) + swz(row, c16);
        cp_async16(dst, src);
    }
    CP_COMMIT();
}

// ---- HMMA GEMM (128x256 CTA tile) + fused exp row/col-sum epilogue ----
__global__ void __launch_bounds__(256, 1) gemm_exp_kernel() {
    // grid: CTA (cj, ti) with ti <= 2*cj+1; idx = cj*(cj+1) + ti
    int idx = blockIdx.x;
    int cj = (int)((sqrtf(4.0f * (float)idx + 1.0f) - 1.0f) * 0.5f);
    while (cj * (cj + 1) > idx) cj--;
    while ((cj + 1) * (cj + 2) <= idx) cj++;
    int ti = idx - cj * (cj + 1);

    extern __shared__ char smem[];
    uint32_t sb = smem_u32(smem);
    int tid = threadIdx.x;
    int wid = tid >> 5, lane = tid & 31;
    int wm = wid >> 2, wn = wid & 3;       // warp tile: rows wm*64, cols wn*64

    const __nv_bfloat16* Xa = g_xb + (size_t)ti * TSM * D;
    const __nv_bfloat16* Xb = g_xb + (size_t)cj * TSN * D;

    float acc[4][8][4];
    #pragma unroll
    for (int mt = 0; mt < 4; mt++)
        #pragma unroll
        for (int nf = 0; nf < 8; nf++)
            #pragma unroll
            for (int q = 0; q < 4; q++) acc[mt][nf][q] = 0.0f;

    int a_row = wm * 64 + (lane & 7) + ((lane >> 3) & 1) * 8;  // + mt*16
    int a_c16h = (lane >> 4);                                   // + k16*2
    int b_row = wn * 64 + (lane & 7) + ((lane >> 4) & 1) * 8;  // + nt*16
    int b_c16h = ((lane >> 3) & 1);                             // + k16*2

    load_stage(sb + 0 * STAGE_BYTES, Xa, Xb, 0, tid);
    load_stage(sb + 1 * STAGE_BYTES, Xa, Xb, 1, tid);

    #pragma unroll 1
    for (int c = 0; c < NCH; c++) {
        if (c + 1 < NCH)
            asm volatile("cp.async.wait_group 1;" ::: "memory");
        else
            asm volatile("cp.async.wait_group 0;" ::: "memory");
        __syncthreads();

        if (c + 2 < NCH)
            load_stage(sb + ((c + 2) % NSTAGE) * STAGE_BYTES, Xa, Xb, c + 2, tid);

        uint32_t abase = sb + (c % NSTAGE) * STAGE_BYTES;
        uint32_t bbase = abase + A_BYTES;
        #pragma unroll
        for (int k16 = 0; k16 < KC / 16; k16++) {
            uint32_t a_r[4][4], b_r[4][4];
            #pragma unroll
            for (int mt = 0; mt < 4; mt++)
                LDM_X4(a_r[mt], abase + swz(a_row + mt * 16, k16 * 2 + a_c16h));
            #pragma unroll
            for (int nt = 0; nt < 4; nt++)
                LDM_X4(b_r[nt], bbase + swz(b_row + nt * 16, k16 * 2 + b_c16h));
            #pragma unroll
            for (int mt = 0; mt < 4; mt++)
                #pragma unroll
                for (int nt = 0; nt < 4; nt++) {
                    MMA16816(acc[mt][nt * 2 + 0], a_r[mt], (b_r[nt] + 0));
                    MMA16816(acc[mt][nt * 2 + 1], a_r[mt], (b_r[nt] + 2));
                }
        }
    }

    // ---- epilogue ----
    // this warp's 64 columns lie entirely in half h = wn>>1 -> col tile:
    int tcol = 2 * cj + (wn >> 1);
    if (tcol < ti) return;                  // below diagonal: discard
    int diag = (tcol == ti);

    int lr = lane >> 2;          // 0..7
    int lc = lane & 3;           // 0..3
    int gr0 = ti * TSM + wm * 64 + lr;           // + mt*16, +8 for half
    int gc0 = cj * TSN + wn * 64 + lc * 2;       // + nf*8, +1

    float jt[8][2];
    #pragma unroll
    for (int nf = 0; nf < 8; nf++) {
        int gj = gc0 + nf * 8;
        jt[nf][0] = g_inv_t[gj];  jt[nf][1] = g_inv_t[gj + 1];
    }

    if (diag) {
        #pragma unroll
        for (int mt = 0; mt < 4; mt++) {
            int gi0 = gr0 + mt * 16, gi1 = gi0 + 8;
            float it0 = g_inv_t[gi0], it1 = g_inv_t[gi1];
            float s0 = 0.0f, s1 = 0.0f;
            #pragma unroll
            for (int nf = 0; nf < 8; nf++) {
                int gj = gc0 + nf * 8;
                float e;
                e = __expf(acc[mt][nf][0] * it0); if (gj     == gi0) e = 0.0f; s0 += e;
                e = __expf(acc[mt][nf][1] * it0); if (gj + 1 == gi0) e = 0.0f; s0 += e;
                e = __expf(acc[mt][nf][2] * it1); if (gj     == gi1) e = 0.0f; s1 += e;
                e = __expf(acc[mt][nf][3] * it1); if (gj + 1 == gi1) e = 0.0f; s1 += e;
            }
            s0 += __shfl_xor_sync(0xFFFFFFFFu, s0, 1);
            s0 += __shfl_xor_sync(0xFFFFFFFFu, s0, 2);
            s1 += __shfl_xor_sync(0xFFFFFFFFu, s1, 1);
            s1 += __shfl_xor_sync(0xFFFFFFFFu, s1, 2);
            if (lc == 0) {
                atomicAdd(&g_denom[gi0], s0);
                atomicAdd(&g_denom[gi1], s1);
            }
        }
    } else {
        float colsum[8][2];
        #pragma unroll
        for (int nf = 0; nf < 8; nf++) { colsum[nf][0] = 0.0f; colsum[nf][1] = 0.0f; }

        #pragma unroll
        for (int mt = 0; mt < 4; mt++) {
            int gi0 = gr0 + mt * 16, gi1 = gi0 + 8;
            float it0 = g_inv_t[gi0], it1 = g_inv_t[gi1];
            float s0 = 0.0f, s1 = 0.0f;
            #pragma unroll
            for (int nf = 0; nf < 8; nf++) {
                float v0 = acc[mt][nf][0], v1 = acc[mt][nf][1];
                float v2 = acc[mt][nf][2], v3 = acc[mt][nf][3];
                s0 += __expf(v0 * it0) + __expf(v1 * it0);
                s1 += __expf(v2 * it1) + __expf(v3 * it1);
                colsum[nf][0] += __expf(v0 * jt[nf][0]) + __expf(v2 * jt[nf][0]);
                colsum[nf][1] += __expf(v1 * jt[nf][1]) + __expf(v3 * jt[nf][1]);
            }
            s0 += __shfl_xor_sync(0xFFFFFFFFu, s0, 1);
            s0 += __shfl_xor_sync(0xFFFFFFFFu, s0, 2);
            s1 += __shfl_xor_sync(0xFFFFFFFFu, s1, 1);
            s1 += __shfl_xor_sync(0xFFFFFFFFu, s1, 2);
            if (lc == 0) {
                atomicAdd(&g_denom[gi0], s0);
                atomicAdd(&g_denom[gi1], s1);
            }
        }
        #pragma unroll
        for (int nf = 0; nf < 8; nf++) {
            #pragma unroll
            for (int i = 0; i < 2; i++) {
                float cs = colsum[nf][i];
                cs += __shfl_xor_sync(0xFFFFFFFFu, cs, 4);
                cs += __shfl_xor_sync(0xFFFFFFFFu, cs, 8);
                cs += __shfl_xor_sync(0xFFFFFFFFu, cs, 16);
                if (lr == 0)
                    atomicAdd(&g_denom[gc0 + nf * 8 + i], cs);
            }
        }
    }
}

__global__ void __launch_bounds__(1024) final_kernel(float* __restrict__ out) {
    __shared__ float sbuf[32];
    int t = threadIdx.x;
    float s = 0.0f;
    #pragma unroll
    for (int k = 0; k < NROW / 1024; k++) {
        int i = t + k * 1024;
        s += __logf(g_denom[i]) - g_pos[i];
    }
    #pragma unroll
    for (int o = 16; o > 0; o >>= 1) s += __shfl_xor_sync(0xFFFFFFFFu, s, o);
    if ((t & 31) == 0) sbuf[t >> 5] = s;
    __syncthreads();
    if (t < 32) {
        float r = sbuf[t];
        #pragma unroll
        for (int o = 16; o > 0; o >>= 1) r += __shfl_xor_sync(0xFFFFFFFFu, r, o);
        if (t == 0) out[0] = r * (1.0f / NROW);
    }
}

extern "C" void kernel_launch(void* const* d_in, const int* in_sizes, int n_in,
                              void* d_out, int out_size) {
    const float* emb1 = (const float*)d_in[0];
    const float* emb2 = (const float*)d_in[1];
    const float* att  = (const float*)d_in[2];

    cudaFuncSetAttribute(gemm_exp_kernel,
                         cudaFuncAttributeMaxDynamicSharedMemorySize, SMEM_TOTAL);

    prep_kernel<<<BATCH / 8, 256>>>(emb1, emb2, att);
    gemm_exp_kernel<<<NCTA, 256, SMEM_TOTAL>>>();
    final_kernel<<<1, 1024>>>((float*)d_out);
}

// round 17
// speedup vs baseline: 2.3486x; 1.1217x over previous
#include <cuda_runtime.h>
#include <cuda_bf16.h>
#include <math.h>
#include <stdint.h>

#define BATCH 4096
#define D     512
#define NROW  8192          // 2B
#define TS    128           // CTA tile (square)
#define KC    64            // k chunk (bf16 elems) = 128 bytes/row
#define NCH   (D / KC)      // 8
#define NT    (NROW / TS)   // 64
#define NTRI  (NT * (NT + 1) / 2)       // 2080 CTAs
#define AB_BYTES (TS * 128)             // 16384 per operand per stage
#define STAGE_BYTES (2 * AB_BYTES)      // 32768
#define NSTAGE 3
#define SMEM_TOTAL (NSTAGE * STAGE_BYTES)  // 98304

// ---- scratch (__device__ globals: allocation-free rule) ----
__device__ __nv_bfloat16 g_xb[NROW * D];   // normalized [e1;e2] bf16, 8 MB
__device__ float g_inv_t[NROW];
__device__ float g_pos[NROW];
__device__ float g_denom[NROW];

__device__ __forceinline__ uint32_t smem_u32(const void* p) {
    uint32_t a;
    asm("{ .reg .u64 t; cvta.to.shared.u64 t, %1; cvt.u32.u64 %0, t; }"
        : "=r"(a) : "l"(p));
    return a;
}
__device__ __forceinline__ void cp_async16(uint32_t dst, const void* src) {
    asm volatile("cp.async.cg.shared.global [%0], [%1], 16;"
                 :: "r"(dst), "l"(src) : "memory");
}
#define CP_COMMIT() asm volatile("cp.async.commit_group;" ::: "memory")

#define LDM_X4(r, addr)                                                     \
    asm volatile("ldmatrix.sync.aligned.m8n8.x4.shared.b16 {%0,%1,%2,%3}, [%4];" \
                 : "=r"(r[0]), "=r"(r[1]), "=r"(r[2]), "=r"(r[3]) : "r"(addr))

#define MMA16816(d, a, b)                                                   \
    asm volatile("mma.sync.aligned.m16n8k16.row.col.f32.bf16.bf16.f32 "     \
                 "{%0,%1,%2,%3}, {%4,%5,%6,%7}, {%8,%9}, {%0,%1,%2,%3};"    \
                 : "+f"(d[0]), "+f"(d[1]), "+f"(d[2]), "+f"(d[3])           \
                 : "r"(a[0]), "r"(a[1]), "r"(a[2]), "r"(a[3]),              \
                   "r"(b[0]), "r"(b[1]))

// ---- prep: warp-per-row, shfl-only reduces ----
__global__ void __launch_bounds__(256) prep_kernel(const float* __restrict__ emb1,
                                                   const float* __restrict__ emb2,
                                                   const float* __restrict__ att) {
    int warp = (blockIdx.x * 256 + threadIdx.x) >> 5;   // row b
    int lane = threadIdx.x & 31;
    if (warp >= BATCH) return;
    int b = warp;

    const float4* a4 = (const float4*)(emb1 + (size_t)b * D);
    const float4* c4 = (const float4*)(emb2 + (size_t)b * D);
    const float4* t4 = (const float4*)(att  + (size_t)b * 256);

    float4 av[4], cv[4];
    float s1 = 0.0f, s2 = 0.0f, sd = 0.0f, sa = 0.0f;
    #pragma unroll
    for (int k = 0; k < 4; k++) {
        int f = lane + k * 32;
        av[k] = a4[f]; cv[k] = c4[f];
        s1 += av[k].x*av[k].x + av[k].y*av[k].y + av[k].z*av[k].z + av[k].w*av[k].w;
        s2 += cv[k].x*cv[k].x + cv[k].y*cv[k].y + cv[k].z*cv[k].z + cv[k].w*cv[k].w;
        sd += av[k].x*cv[k].x + av[k].y*cv[k].y + av[k].z*cv[k].z + av[k].w*cv[k].w;
    }
    #pragma unroll
    for (int k = 0; k < 2; k++) {
        float4 v = t4[lane + k * 32];
        sa += v.x + v.y + v.z + v.w;
    }
    #pragma unroll
    for (int o = 16; o > 0; o >>= 1) {
        s1 += __shfl_xor_sync(0xFFFFFFFFu, s1, o);
        s2 += __shfl_xor_sync(0xFFFFFFFFu, s2, o);
        sd += __shfl_xor_sync(0xFFFFFFFFu, sd, o);
        sa += __shfl_xor_sync(0xFFFFFFFFu, sa, o);
    }

    float r1 = 1.0f / fmaxf(sqrtf(s1), 1e-12f);
    float r2 = 1.0f / fmaxf(sqrtf(s2), 1e-12f);
    float invt = 1.0f / (0.07f * (1.0f + 0.5f * (sa * (1.0f / 256.0f))));

    uint2* x1 = (uint2*)(g_xb + (size_t)b * D);
    uint2* x2 = (uint2*)(g_xb + (size_t)(b + BATCH) * D);
    #pragma unroll
    for (int k = 0; k < 4; k++) {
        int f = lane + k * 32;
        __nv_bfloat162 p0 = __floats2bfloat162_rn(av[k].x * r1, av[k].y * r1);
        __nv_bfloat162 p1 = __floats2bfloat162_rn(av[k].z * r1, av[k].w * r1);
        uint2 u; u.x = *(uint32_t*)&p0; u.y = *(uint32_t*)&p1;
        x1[f] = u;
        p0 = __floats2bfloat162_rn(cv[k].x * r2, cv[k].y * r2);
        p1 = __floats2bfloat162_rn(cv[k].z * r2, cv[k].w * r2);
        u.x = *(uint32_t*)&p0; u.y = *(uint32_t*)&p1;
        x2[f] = u;
    }
    if (lane == 0) {
        g_inv_t[b] = invt;  g_inv_t[b + BATCH] = invt;
        float p = sd * r1 * r2 * invt;
        g_pos[b] = p;       g_pos[b + BATCH] = p;
        g_denom[b] = 0.0f;  g_denom[b + BATCH] = 0.0f;
    }
}

// swizzled byte offset within a 128-row x 128-byte operand buffer
__device__ __forceinline__ uint32_t swz(int row, int c16) {
    return (uint32_t)(row * 128 + ((c16 ^ (row & 7)) * 16));
}

__device__ __forceinline__ void load_stage(uint32_t base,
                                           const __nv_bfloat16* Xa,
                                           const __nv_bfloat16* Xb,
                                           int chunk, int tid) {
    #pragma unroll
    for (int it = 0; it < 16; it++) {
        int idx = tid + it * 128;          // 0..2047
        int isA = idx < 1024;
        int j = isA ? idx : idx - 1024;
        int row = j >> 3, c16 = j & 7;
        const __nv_bfloat16* src =
            (isA ? Xa : Xb) + (size_t)row * D + chunk * KC + c16 * 8;
        uint32_t dst = base + (isA ? 0u : (uint32_t)AB_BYTES) + swz(row, c16);
        cp_async16(dst, src);
    }
    CP_COMMIT();
}

// ---- HMMA GEMM tile (128x128, 4 warps of 64x64) + fused exp epilogue ----
__global__ void __launch_bounds__(128, 2) gemm_exp_kernel() {
    // triangular 1D grid -> (ti, tj), ti <= tj
    int idx = blockIdx.x;
    int ti = (int)((129.0f - sqrtf(16641.0f - 8.0f * (float)idx)) * 0.5f);
    while (ti * (129 - ti) / 2 > idx) ti--;
    while ((ti + 1) * (129 - (ti + 1)) / 2 <= idx) ti++;
    int tj = ti + (idx - ti * (129 - ti) / 2);

    extern __shared__ char smem[];
    uint32_t sb = smem_u32(smem);
    int tid = threadIdx.x;
    int wid = tid >> 5, lane = tid & 31;
    int wm = wid >> 1, wn = wid & 1;       // warp tile: rows wm*64, cols wn*64

    const __nv_bfloat16* Xa = g_xb + (size_t)ti * TS * D;
    const __nv_bfloat16* Xb = g_xb + (size_t)tj * TS * D;

    float acc[4][8][4];
    #pragma unroll
    for (int mt = 0; mt < 4; mt++)
        #pragma unroll
        for (int nf = 0; nf < 8; nf++)
            #pragma unroll
            for (int q = 0; q < 4; q++) acc[mt][nf][q] = 0.0f;

    int a_row = wm * 64 + (lane & 7) + ((lane >> 3) & 1) * 8;  // + mt*16
    int a_c16h = (lane >> 4);                                   // + k16*2
    int b_row = wn * 64 + (lane & 7) + ((lane >> 4) & 1) * 8;  // + nt*16
    int b_c16h = ((lane >> 3) & 1);                             // + k16*2

    load_stage(sb + 0 * STAGE_BYTES, Xa, Xb, 0, tid);
    load_stage(sb + 1 * STAGE_BYTES, Xa, Xb, 1, tid);

    #pragma unroll 1
    for (int c = 0; c < NCH; c++) {
        if (c + 1 < NCH)
            asm volatile("cp.async.wait_group 1;" ::: "memory");
        else
            asm volatile("cp.async.wait_group 0;" ::: "memory");
        __syncthreads();

        if (c + 2 < NCH)
            load_stage(sb + ((c + 2) % NSTAGE) * STAGE_BYTES, Xa, Xb, c + 2, tid);

        uint32_t abase = sb + (c % NSTAGE) * STAGE_BYTES;
        uint32_t bbase = abase + AB_BYTES;
        #pragma unroll
        for (int k16 = 0; k16 < KC / 16; k16++) {
            uint32_t a_r[4][4], b_r[4][4];
            #pragma unroll
            for (int mt = 0; mt < 4; mt++)
                LDM_X4(a_r[mt], abase + swz(a_row + mt * 16, k16 * 2 + a_c16h));
            #pragma unroll
            for (int nt = 0; nt < 4; nt++)
                LDM_X4(b_r[nt], bbase + swz(b_row + nt * 16, k16 * 2 + b_c16h));
            #pragma unroll
            for (int mt = 0; mt < 4; mt++)
                #pragma unroll
                for (int nt = 0; nt < 4; nt++) {
                    MMA16816(acc[mt][nt * 2 + 0], a_r[mt], (b_r[nt] + 0));
                    MMA16816(acc[mt][nt * 2 + 1], a_r[mt], (b_r[nt] + 2));
                }
        }
    }

    // ---- epilogue ----
    int lr = lane >> 2;          // 0..7
    int lc = lane & 3;           // 0..3
    int gr0 = ti * TS + wm * 64 + lr;            // + mt*16, +8 for half
    int gc0 = tj * TS + wn * 64 + lc * 2;        // + nf*8, +1

    float jt[8][2];
    #pragma unroll
    for (int nf = 0; nf < 8; nf++) {
        int gj = gc0 + nf * 8;
        jt[nf][0] = g_inv_t[gj];  jt[nf][1] = g_inv_t[gj + 1];
    }

    if (ti == tj) {
        #pragma unroll
        for (int mt = 0; mt < 4; mt++) {
            int gi0 = gr0 + mt * 16, gi1 = gi0 + 8;
            float it0 = g_inv_t[gi0], it1 = g_inv_t[gi1];
            float s0 = 0.0f, s1 = 0.0f;
            #pragma unroll
            for (int nf = 0; nf < 8; nf++) {
                int gj = gc0 + nf * 8;
                float e;
                e = __expf(acc[mt][nf][0] * it0); if (gj     == gi0) e = 0.0f; s0 += e;
                e = __expf(acc[mt][nf][1] * it0); if (gj + 1 == gi0) e = 0.0f; s0 += e;
                e = __expf(acc[mt][nf][2] * it1); if (gj     == gi1) e = 0.0f; s1 += e;
                e = __expf(acc[mt][nf][3] * it1); if (gj + 1 == gi1) e = 0.0f; s1 += e;
            }
            s0 += __shfl_xor_sync(0xFFFFFFFFu, s0, 1);
            s0 += __shfl_xor_sync(0xFFFFFFFFu, s0, 2);
            s1 += __shfl_xor_sync(0xFFFFFFFFu, s1, 1);
            s1 += __shfl_xor_sync(0xFFFFFFFFu, s1, 2);
            if (lc == 0) {
                atomicAdd(&g_denom[gi0], s0);
                atomicAdd(&g_denom[gi1], s1);
            }
        }
    } else {
        float colsum[8][2];
        #pragma unroll
        for (int nf = 0; nf < 8; nf++) { colsum[nf][0] = 0.0f; colsum[nf][1] = 0.0f; }

        #pragma unroll
        for (int mt = 0; mt < 4; mt++) {
            int gi0 = gr0 + mt * 16, gi1 = gi0 + 8;
            float it0 = g_inv_t[gi0], it1 = g_inv_t[gi1];
            float s0 = 0.0f, s1 = 0.0f;
            #pragma unroll
            for (int nf = 0; nf < 8; nf++) {
                float v0 = acc[mt][nf][0], v1 = acc[mt][nf][1];
                float v2 = acc[mt][nf][2], v3 = acc[mt][nf][3];
                s0 += __expf(v0 * it0) + __expf(v1 * it0);
                s1 += __expf(v2 * it1) + __expf(v3 * it1);
                colsum[nf][0] += __expf(v0 * jt[nf][0]) + __expf(v2 * jt[nf][0]);
                colsum[nf][1] += __expf(v1 * jt[nf][1]) + __expf(v3 * jt[nf][1]);
            }
            s0 += __shfl_xor_sync(0xFFFFFFFFu, s0, 1);
            s0 += __shfl_xor_sync(0xFFFFFFFFu, s0, 2);
            s1 += __shfl_xor_sync(0xFFFFFFFFu, s1, 1);
            s1 += __shfl_xor_sync(0xFFFFFFFFu, s1, 2);
            if (lc == 0) {
                atomicAdd(&g_denom[gi0], s0);
                atomicAdd(&g_denom[gi1], s1);
            }
        }
        #pragma unroll
        for (int nf = 0; nf < 8; nf++) {
            #pragma unroll
            for (int i = 0; i < 2; i++) {
                float cs = colsum[nf][i];
                cs += __shfl_xor_sync(0xFFFFFFFFu, cs, 4);
                cs += __shfl_xor_sync(0xFFFFFFFFu, cs, 8);
                cs += __shfl_xor_sync(0xFFFFFFFFu, cs, 16);
                if (lr == 0)
                    atomicAdd(&g_denom[gc0 + nf * 8 + i], cs);
            }
        }
    }
}

__global__ void __launch_bounds__(1024) final_kernel(float* __restrict__ out) {
    __shared__ float sbuf[32];
    int t = threadIdx.x;
    float s = 0.0f;
    #pragma unroll
    for (int k = 0; k < NROW / 1024; k++) {
        int i = t + k * 1024;
        s += __logf(g_denom[i]) - g_pos[i];
    }
    #pragma unroll
    for (int o = 16; o > 0; o >>= 1) s += __shfl_xor_sync(0xFFFFFFFFu, s, o);
    if ((t & 31) == 0) sbuf[t >> 5] = s;
    __syncthreads();
    if (t < 32) {
        float r = sbuf[t];
        #pragma unroll
        for (int o = 16; o > 0; o >>= 1) r += __shfl_xor_sync(0xFFFFFFFFu, r, o);
        if (t == 0) out[0] = r * (1.0f / NROW);
    }
}

extern "C" void kernel_launch(void* const* d_in, const int* in_sizes, int n_in,
                              void* d_out, int out_size) {
    const float* emb1 = (const float*)d_in[0];
    const float* emb2 = (const float*)d_in[1];
    const float* att  = (const float*)d_in[2];

    cudaFuncSetAttribute(gemm_exp_kernel,
                         cudaFuncAttributeMaxDynamicSharedMemorySize, SMEM_TOTAL);

    prep_kernel<<<BATCH / 8, 256>>>(emb1, emb2, att);
    gemm_exp_kernel<<<NTRI, 128, SMEM_TOTAL>>>();
    final_kernel<<<1, 1024>>>((float*)d_out);
}